// round 1
// baseline (speedup 1.0000x reference)
#include <cuda_runtime.h>
#include <cstdint>

#define MAXB 8
#define JT 256

// ---------------- scratch (device globals; no allocation) ----------------
__device__ double g_Sw[MAXB];
__device__ double g_Sp[MAXB][3];
__device__ double g_Sg[MAXB][3];
__device__ double g_M[MAXB][9];     // raw moments: sum w * p_a * g_b
__device__ double g_Spp[MAXB];
__device__ double g_Sgg[MAXB];
__device__ double g_analytic[MAXB];
__device__ float  g_R[MAXB][9];
__device__ float  g_mup[MAXB][3];
__device__ float  g_mug[MAXB][3];
__device__ double g_losspts;
__device__ double g_cross;

__device__ __forceinline__ float fsqrt_fast(float x) {
    float r; asm("sqrt.approx.f32 %0, %1;" : "=f"(r) : "f"(x)); return r;
}

__device__ __forceinline__ float block_reduce_f(float v) {
    #pragma unroll
    for (int o = 16; o > 0; o >>= 1) v += __shfl_down_sync(0xffffffffu, v, o);
    __shared__ float s[32];
    int lane = threadIdx.x & 31, wid = threadIdx.x >> 5;
    if (lane == 0) s[wid] = v;
    __syncthreads();
    int nw = (blockDim.x + 31) >> 5;
    v = (threadIdx.x < nw) ? s[threadIdx.x] : 0.0f;
    if (wid == 0) {
        #pragma unroll
        for (int o = 16; o > 0; o >>= 1) v += __shfl_down_sync(0xffffffffu, v, o);
    }
    return v;  // valid in thread 0
}

// ---------------- Kernel A: per-batch moment reductions ----------------
__global__ void reduce_kernel(const float* __restrict__ p, const float* __restrict__ gt,
                              const float* __restrict__ w, int N) {
    int b = blockIdx.x;
    const float* pb = p  + (size_t)b * N * 3;
    const float* gb = gt + (size_t)b * N * 3;
    const float* wb = w  + (size_t)b * N;

    double acc[18];
    #pragma unroll
    for (int k = 0; k < 18; k++) acc[k] = 0.0;

    for (int i = threadIdx.x; i < N; i += blockDim.x) {
        double wi = (double)wb[i];
        double px = pb[3*i], py = pb[3*i+1], pz = pb[3*i+2];
        double gx = gb[3*i], gy = gb[3*i+1], gz = gb[3*i+2];
        acc[0] += wi;
        acc[1] += wi*px; acc[2] += wi*py; acc[3] += wi*pz;
        acc[4] += wi*gx; acc[5] += wi*gy; acc[6] += wi*gz;
        acc[7]  += wi*px*gx; acc[8]  += wi*px*gy; acc[9]  += wi*px*gz;
        acc[10] += wi*py*gx; acc[11] += wi*py*gy; acc[12] += wi*py*gz;
        acc[13] += wi*pz*gx; acc[14] += wi*pz*gy; acc[15] += wi*pz*gz;
        acc[16] += wi*(px*px + py*py + pz*pz);
        acc[17] += wi*(gx*gx + gy*gy + gz*gz);
    }

    __shared__ double sred[256];
    for (int k = 0; k < 18; k++) {
        sred[threadIdx.x] = acc[k];
        __syncthreads();
        for (int off = blockDim.x >> 1; off > 0; off >>= 1) {
            if (threadIdx.x < off) sred[threadIdx.x] += sred[threadIdx.x + off];
            __syncthreads();
        }
        if (threadIdx.x == 0) {
            double v = sred[0];
            if      (k == 0)  g_Sw[b] = v;
            else if (k <= 3)  g_Sp[b][k-1]  = v;
            else if (k <= 6)  g_Sg[b][k-4]  = v;
            else if (k <= 15) g_M[b][k-7]   = v;
            else if (k == 16) g_Spp[b] = v;
            else              g_Sgg[b] = v;
        }
        __syncthreads();
    }
    if (b == 0 && threadIdx.x == 0) { g_losspts = 0.0; g_cross = 0.0; }
}

// ---------------- Kernel B: Kabsch solve (3x3 SVD via Jacobi on M^T M) ----------------
__global__ void solve_kernel(int B) {
    int b = threadIdx.x;
    if (b >= B) return;

    double Sw = g_Sw[b];
    double sp[3] = { g_Sp[b][0], g_Sp[b][1], g_Sp[b][2] };
    double sg[3] = { g_Sg[b][0], g_Sg[b][1], g_Sg[b][2] };
    double invSw = 1.0 / Sw;

    // Centered cross-covariance: M[i][j] = sum w * (p-mu_p)_i (g-mu_g)_j
    double M[3][3];
    #pragma unroll
    for (int i = 0; i < 3; i++)
        #pragma unroll
        for (int j = 0; j < 3; j++)
            M[i][j] = g_M[b][i*3+j] - sp[i]*sg[j]*invSw;

    // A = M^T M  (symmetric PSD)
    double A[3][3];
    #pragma unroll
    for (int i = 0; i < 3; i++)
        #pragma unroll
        for (int j = 0; j < 3; j++)
            A[i][j] = M[0][i]*M[0][j] + M[1][i]*M[1][j] + M[2][i]*M[2][j];

    double V[3][3] = {{1,0,0},{0,1,0},{0,0,1}};

    // Cyclic Jacobi sweeps (double precision; fixed iteration count -> deterministic)
    for (int sweep = 0; sweep < 25; sweep++) {
        #pragma unroll
        for (int pair = 0; pair < 3; pair++) {
            int pp = (pair == 0) ? 0 : (pair == 1) ? 0 : 1;
            int qq = (pair == 0) ? 1 : (pair == 1) ? 2 : 2;
            double apq = A[pp][qq];
            if (fabs(apq) < 1e-300) continue;
            double theta = (A[qq][qq] - A[pp][pp]) / (2.0 * apq);
            double t = ((theta >= 0.0) ? 1.0 : -1.0) / (fabs(theta) + sqrt(theta*theta + 1.0));
            double c = 1.0 / sqrt(t*t + 1.0);
            double s = t * c;
            double app = A[pp][pp], aq2 = A[qq][qq];
            A[pp][pp] = app - t * apq;
            A[qq][qq] = aq2 + t * apq;
            A[pp][qq] = A[qq][pp] = 0.0;
            int r = 3 - pp - qq;
            double arp = A[r][pp], arq = A[r][qq];
            A[r][pp] = A[pp][r] = c*arp - s*arq;
            A[r][qq] = A[qq][r] = s*arp + c*arq;
            #pragma unroll
            for (int k = 0; k < 3; k++) {
                double vkp = V[k][pp], vkq = V[k][qq];
                V[k][pp] = c*vkp - s*vkq;
                V[k][qq] = s*vkp + c*vkq;
            }
        }
    }

    double lam[3] = { A[0][0], A[1][1], A[2][2] };
    int id[3] = {0, 1, 2};
    if (lam[id[0]] < lam[id[1]]) { int t = id[0]; id[0] = id[1]; id[1] = t; }
    if (lam[id[0]] < lam[id[2]]) { int t = id[0]; id[0] = id[2]; id[2] = t; }
    if (lam[id[1]] < lam[id[2]]) { int t = id[1]; id[1] = id[2]; id[2] = t; }

    double U[3][3];
    #pragma unroll
    for (int k = 0; k < 3; k++) {
        double l = lam[id[k]];
        double sig = sqrt(l > 0.0 ? l : 0.0);
        double inv = (sig > 1e-12) ? 1.0 / sig : 0.0;
        #pragma unroll
        for (int i = 0; i < 3; i++)
            U[i][k] = (M[i][0]*V[0][id[k]] + M[i][1]*V[1][id[k]] + M[i][2]*V[2][id[k]]) * inv;
    }

    double detM = M[0][0]*(M[1][1]*M[2][2] - M[1][2]*M[2][1])
                - M[0][1]*(M[1][0]*M[2][2] - M[1][2]*M[2][0])
                + M[0][2]*(M[1][0]*M[2][1] - M[1][1]*M[2][0]);
    double f2 = (detM < 0.0) ? -1.0 : 1.0;

    // R = U diag(1,1,f2) Vs^T, Vs columns sorted by descending sigma
    #pragma unroll
    for (int i = 0; i < 3; i++)
        #pragma unroll
        for (int j = 0; j < 3; j++)
            g_R[b][i*3+j] = (float)(U[i][0]*V[j][id[0]] + U[i][1]*V[j][id[1]] + f2*U[i][2]*V[j][id[2]]);

    #pragma unroll
    for (int i = 0; i < 3; i++) {
        g_mup[b][i] = (float)(sp[i] * invSw);
        g_mug[b][i] = (float)(sg[i] * invSw);
    }

    // Analytic part of bond numerator: sum_ij wi wj (dp^2 + dg^2)
    g_analytic[b] = 2.0 * Sw * (g_Spp[b] + g_Sgg[b])
                  - 2.0 * (sp[0]*sp[0] + sp[1]*sp[1] + sp[2]*sp[2]
                         + sg[0]*sg[0] + sg[1]*sg[1] + sg[2]*sg[2]);
}

// ---------------- Kernel C: point loss sum w * ||p - (R(g-mug) + mup)|| ----------------
__global__ void pts_kernel(const float* __restrict__ p, const float* __restrict__ gt,
                           const float* __restrict__ w, int N) {
    int b = blockIdx.x;
    const float* pb = p  + (size_t)b * N * 3;
    const float* gb = gt + (size_t)b * N * 3;
    const float* wb = w  + (size_t)b * N;

    float r00 = g_R[b][0], r01 = g_R[b][1], r02 = g_R[b][2];
    float r10 = g_R[b][3], r11 = g_R[b][4], r12 = g_R[b][5];
    float r20 = g_R[b][6], r21 = g_R[b][7], r22 = g_R[b][8];
    float m0 = g_mup[b][0], m1 = g_mup[b][1], m2 = g_mup[b][2];
    float u0 = g_mug[b][0], u1 = g_mug[b][1], u2 = g_mug[b][2];

    float acc = 0.0f;
    for (int i = threadIdx.x; i < N; i += blockDim.x) {
        float gx = gb[3*i]   - u0;
        float gy = gb[3*i+1] - u1;
        float gz = gb[3*i+2] - u2;
        float ax = fmaf(r00, gx, fmaf(r01, gy, r02*gz)) + m0;
        float ay = fmaf(r10, gx, fmaf(r11, gy, r12*gz)) + m1;
        float az = fmaf(r20, gx, fmaf(r21, gy, r22*gz)) + m2;
        float dx = pb[3*i]   - ax;
        float dy = pb[3*i+1] - ay;
        float dz = pb[3*i+2] - az;
        float nsq = fmaf(dx, dx, fmaf(dy, dy, dz*dz));
        acc += wb[i] * fsqrt_fast(nsq);
    }
    float tot = block_reduce_f(acc);
    if (threadIdx.x == 0) atomicAdd(&g_losspts, (double)tot);
}

// ---------------- Kernel D: bond cross term sum_ij wi wj * dp * dg ----------------
// grid: (j-chunks, i-tiles, B); block: JT threads, each owns one i, loops j-chunk in smem.
__global__ void bond_kernel(const float* __restrict__ p, const float* __restrict__ gt,
                            const float* __restrict__ w, int N) {
    __shared__ float4 shp[JT];
    __shared__ float4 shg[JT];

    int b  = blockIdx.z;
    int j0 = blockIdx.x * JT;
    int i  = blockIdx.y * JT + threadIdx.x;
    const size_t base = (size_t)b * N;

    int j = j0 + threadIdx.x;
    if (j < N) {
        const float* pj = p  + (base + j) * 3;
        const float* gj = gt + (base + j) * 3;
        shp[threadIdx.x] = make_float4(pj[0], pj[1], pj[2], w[base + j]);
        shg[threadIdx.x] = make_float4(gj[0], gj[1], gj[2], 0.0f);
    } else {
        shp[threadIdx.x] = make_float4(0.f, 0.f, 0.f, 0.f);  // w=0 -> no contribution
        shg[threadIdx.x] = make_float4(0.f, 0.f, 0.f, 0.f);
    }
    __syncthreads();

    float xi = 0.f, yi = 0.f, zi = 0.f, gxi = 0.f, gyi = 0.f, gzi = 0.f, wi = 0.f;
    if (i < N) {
        const float* pi = p  + (base + i) * 3;
        const float* gi = gt + (base + i) * 3;
        xi = pi[0]; yi = pi[1]; zi = pi[2];
        gxi = gi[0]; gyi = gi[1]; gzi = gi[2];
        wi = w[base + i];
    }

    float acc = 0.0f;
    #pragma unroll 8
    for (int jj = 0; jj < JT; jj++) {
        float4 P = shp[jj];
        float4 G = shg[jj];
        float dx = xi - P.x, dy = yi - P.y, dz = zi - P.z;
        float dp2 = fmaf(dx, dx, fmaf(dy, dy, dz*dz));
        float ex = gxi - G.x, ey = gyi - G.y, ez = gzi - G.z;
        float dg2 = fmaf(ex, ex, fmaf(ey, ey, ez*ez));
        float s = fsqrt_fast(dp2 * dg2);   // dp*dg with ONE sqrt
        acc = fmaf(P.w, s, acc);
    }
    acc *= wi;

    float tot = block_reduce_f(acc);
    if (threadIdx.x == 0) atomicAdd(&g_cross, (double)tot);
}

// ---------------- Kernel E: finalize ----------------
__global__ void final_kernel(const float* __restrict__ ht, float* __restrict__ out,
                             int B, int outn) {
    __shared__ double loss_sh;
    if (threadIdx.x == 0) {
        double totW = 0.0, den = 0.0, an = 0.0;
        for (int b = 0; b < B; b++) {
            double s = g_Sw[b];
            totW += s;
            den  += s * s;
            an   += g_analytic[b];
        }
        double loss_pts  = g_losspts / totW;
        double loss_bond = (an - 2.0 * g_cross) / den;
        loss_sh = loss_pts + 1.0 * loss_bond;   // ALPHA_BOND = 1
    }
    __syncthreads();
    int b = threadIdx.x;
    if (b < outn && b < B) {
        double h = (double)ht[b];
        out[b] = (float)((h*h + 256.0) / ((h + 16.0)*(h + 16.0)) * loss_sh);
    }
}

// ---------------- launcher ----------------
extern "C" void kernel_launch(void* const* d_in, const int* in_sizes, int n_in,
                              void* d_out, int out_size) {
    const float* p  = (const float*)d_in[0];  // xpred_l [B,N,3]
    const float* g  = (const float*)d_in[1];  // xGT_l   [B,N,3]
    const float* ht = (const float*)d_in[2];  // ht      [B]
    const float* w  = (const float*)d_in[3];  // w_l     [B,N]

    int B = in_sizes[2];
    if (B > MAXB) B = MAXB;
    int N = in_sizes[3] / B;

    reduce_kernel<<<B, 256>>>(p, g, w, N);
    solve_kernel<<<1, 32>>>(B);
    pts_kernel<<<B, 256>>>(p, g, w, N);

    int tiles = (N + JT - 1) / JT;
    dim3 gridD(tiles, tiles, B);
    bond_kernel<<<gridD, JT>>>(p, g, w, N);

    final_kernel<<<1, 32>>>(ht, (float*)d_out, B, out_size);
}

// round 3
// speedup vs baseline: 3.5518x; 3.5518x over previous
#include <cuda_runtime.h>
#include <cstdint>

#define MAXB 8
#define JT 256

// ---------------- scratch (device globals; no allocation) ----------------
__device__ double g_Sw[MAXB];
__device__ double g_Sp[MAXB][3];
__device__ double g_Sg[MAXB][3];
__device__ double g_M[MAXB][9];     // raw moments: sum w * p_a * g_b
__device__ double g_Spp[MAXB];
__device__ double g_Sgg[MAXB];
__device__ double g_analytic[MAXB];
__device__ float  g_R[MAXB][9];
__device__ float  g_mup[MAXB][3];
__device__ float  g_mug[MAXB][3];
__device__ double g_losspts;
__device__ double g_cross;

__device__ __forceinline__ float fsqrt_fast(float x) {
    float r; asm("sqrt.approx.f32 %0, %1;" : "=f"(r) : "f"(x)); return r;
}

__device__ __forceinline__ float block_reduce_f(float v) {
    #pragma unroll
    for (int o = 16; o > 0; o >>= 1) v += __shfl_down_sync(0xffffffffu, v, o);
    __shared__ float s[32];
    int lane = threadIdx.x & 31, wid = threadIdx.x >> 5;
    if (lane == 0) s[wid] = v;
    __syncthreads();
    int nw = (blockDim.x + 31) >> 5;
    v = (threadIdx.x < nw) ? s[threadIdx.x] : 0.0f;
    if (wid == 0) {
        #pragma unroll
        for (int o = 16; o > 0; o >>= 1) v += __shfl_down_sync(0xffffffffu, v, o);
    }
    return v;  // valid in thread 0
}

// ---------------- Kernel A: per-batch moment reductions (float fast path) ----------------
__global__ void reduce_kernel(const float* __restrict__ p, const float* __restrict__ gt,
                              const float* __restrict__ w, int N) {
    int b = blockIdx.x;
    const float* pb = p  + (size_t)b * N * 3;
    const float* gb = gt + (size_t)b * N * 3;
    const float* wb = w  + (size_t)b * N;

    float acc[18];
    #pragma unroll
    for (int k = 0; k < 18; k++) acc[k] = 0.0f;

    for (int i = threadIdx.x; i < N; i += blockDim.x) {
        float wi = wb[i];
        float px = pb[3*i], py = pb[3*i+1], pz = pb[3*i+2];
        float gx = gb[3*i], gy = gb[3*i+1], gz = gb[3*i+2];
        float wpx = wi*px, wpy = wi*py, wpz = wi*pz;
        acc[0] += wi;
        acc[1] += wpx; acc[2] += wpy; acc[3] += wpz;
        acc[4] = fmaf(wi, gx, acc[4]); acc[5] = fmaf(wi, gy, acc[5]); acc[6] = fmaf(wi, gz, acc[6]);
        acc[7]  = fmaf(wpx, gx, acc[7]);  acc[8]  = fmaf(wpx, gy, acc[8]);  acc[9]  = fmaf(wpx, gz, acc[9]);
        acc[10] = fmaf(wpy, gx, acc[10]); acc[11] = fmaf(wpy, gy, acc[11]); acc[12] = fmaf(wpy, gz, acc[12]);
        acc[13] = fmaf(wpz, gx, acc[13]); acc[14] = fmaf(wpz, gy, acc[14]); acc[15] = fmaf(wpz, gz, acc[15]);
        acc[16] = fmaf(wpx, px, fmaf(wpy, py, fmaf(wpz, pz, acc[16])));
        acc[17] = fmaf(wi*gx, gx, fmaf(wi*gy, gy, fmaf(wi*gz, gz, acc[17])));
    }

    // warp-level shuffle reduce all 18
    #pragma unroll
    for (int k = 0; k < 18; k++) {
        #pragma unroll
        for (int o = 16; o > 0; o >>= 1)
            acc[k] += __shfl_down_sync(0xffffffffu, acc[k], o);
    }

    __shared__ float s[8][18];
    int lane = threadIdx.x & 31, wid = threadIdx.x >> 5;
    if (lane == 0) {
        #pragma unroll
        for (int k = 0; k < 18; k++) s[wid][k] = acc[k];
    }
    __syncthreads();

    if (threadIdx.x < 18) {
        int k = threadIdx.x;
        double v = 0.0;
        #pragma unroll
        for (int ww = 0; ww < 8; ww++) v += (double)s[ww][k];
        if      (k == 0)  g_Sw[b] = v;
        else if (k <= 3)  g_Sp[b][k-1]  = v;
        else if (k <= 6)  g_Sg[b][k-4]  = v;
        else if (k <= 15) g_M[b][k-7]   = v;
        else if (k == 16) g_Spp[b] = v;
        else              g_Sgg[b] = v;
    }
    if (b == 0 && threadIdx.x == 0) { g_losspts = 0.0; g_cross = 0.0; }
}

// ---------------- Kernel B: Kabsch solve — float Jacobi on M^T M ----------------
__global__ void solve_kernel(int B) {
    int b = threadIdx.x;
    if (b >= B) return;

    double Sw = g_Sw[b];
    double invSw = 1.0 / Sw;
    double sp[3] = { g_Sp[b][0], g_Sp[b][1], g_Sp[b][2] };
    double sg[3] = { g_Sg[b][0], g_Sg[b][1], g_Sg[b][2] };

    // Centered cross-covariance in double (cancellation-sensitive step)
    double Md[3][3];
    #pragma unroll
    for (int i = 0; i < 3; i++)
        #pragma unroll
        for (int j = 0; j < 3; j++)
            Md[i][j] = g_M[b][i*3+j] - sp[i]*sg[j]*invSw;

    // Scale-normalize and drop to float
    double mx = 0.0;
    #pragma unroll
    for (int i = 0; i < 3; i++)
        #pragma unroll
        for (int j = 0; j < 3; j++)
            mx = fmax(mx, fabs(Md[i][j]));
    double invmx = (mx > 0.0) ? 1.0 / mx : 0.0;

    float M[3][3];
    #pragma unroll
    for (int i = 0; i < 3; i++)
        #pragma unroll
        for (int j = 0; j < 3; j++)
            M[i][j] = (float)(Md[i][j] * invmx);

    // A = M^T M (symmetric PSD, entries O(1))
    float A[3][3];
    #pragma unroll
    for (int i = 0; i < 3; i++)
        #pragma unroll
        for (int j = 0; j < 3; j++)
            A[i][j] = M[0][i]*M[0][j] + M[1][i]*M[1][j] + M[2][i]*M[2][j];

    float V[3][3] = {{1,0,0},{0,1,0},{0,0,1}};

    // Cyclic Jacobi in float (fixed count -> deterministic, quadratic conv.)
    for (int sweep = 0; sweep < 12; sweep++) {
        #pragma unroll
        for (int pair = 0; pair < 3; pair++) {
            int pp = (pair == 2) ? 1 : 0;
            int qq = (pair == 0) ? 1 : 2;
            float apq = A[pp][qq];
            if (fabsf(apq) < 1e-20f) continue;
            float theta = (A[qq][qq] - A[pp][pp]) / (2.0f * apq);
            float t = ((theta >= 0.0f) ? 1.0f : -1.0f) /
                      (fabsf(theta) + fsqrt_fast(fmaf(theta, theta, 1.0f)));
            float c = rsqrtf(fmaf(t, t, 1.0f));
            float s = t * c;
            float app = A[pp][pp], aq2 = A[qq][qq];
            A[pp][pp] = app - t * apq;
            A[qq][qq] = aq2 + t * apq;
            A[pp][qq] = A[qq][pp] = 0.0f;
            int r = 3 - pp - qq;
            float arp = A[r][pp], arq = A[r][qq];
            A[r][pp] = A[pp][r] = c*arp - s*arq;
            A[r][qq] = A[qq][r] = s*arp + c*arq;
            #pragma unroll
            for (int k = 0; k < 3; k++) {
                float vkp = V[k][pp], vkq = V[k][qq];
                V[k][pp] = c*vkp - s*vkq;
                V[k][qq] = s*vkp + c*vkq;
            }
        }
    }

    // Sort eigenvalues descending
    float lam[3] = { A[0][0], A[1][1], A[2][2] };
    int id[3] = {0, 1, 2};
    if (lam[id[0]] < lam[id[1]]) { int t = id[0]; id[0] = id[1]; id[1] = t; }
    if (lam[id[0]] < lam[id[2]]) { int t = id[0]; id[0] = id[2]; id[2] = t; }
    if (lam[id[1]] < lam[id[2]]) { int t = id[1]; id[1] = id[2]; id[2] = t; }

    // U columns: u_k = normalize(M v_k) for k=0,1; u_2 = u_0 x u_1.
    // With u2 = cross(u0,u1), det(U)=+1 and the reference's diag(1,1,f2) flip
    // is algebraically absorbed (f2 * sign(detM) = +1), so R = U V^T directly.
    float U[3][3];
    #pragma unroll
    for (int k = 0; k < 2; k++) {
        float v0 = V[0][id[k]], v1 = V[1][id[k]], v2 = V[2][id[k]];
        float u0 = M[0][0]*v0 + M[0][1]*v1 + M[0][2]*v2;
        float u1 = M[1][0]*v0 + M[1][1]*v1 + M[1][2]*v2;
        float u2 = M[2][0]*v0 + M[2][1]*v1 + M[2][2]*v2;
        float inv = rsqrtf(fmaxf(u0*u0 + u1*u1 + u2*u2, 1e-30f));
        U[0][k] = u0*inv; U[1][k] = u1*inv; U[2][k] = u2*inv;
    }
    U[0][2] = U[1][0]*U[2][1] - U[2][0]*U[1][1];
    U[1][2] = U[2][0]*U[0][1] - U[0][0]*U[2][1];
    U[2][2] = U[0][0]*U[1][1] - U[1][0]*U[0][1];

    #pragma unroll
    for (int i = 0; i < 3; i++)
        #pragma unroll
        for (int j = 0; j < 3; j++)
            g_R[b][i*3+j] = U[i][0]*V[j][id[0]] + U[i][1]*V[j][id[1]] + U[i][2]*V[j][id[2]];

    #pragma unroll
    for (int i = 0; i < 3; i++) {
        g_mup[b][i] = (float)(sp[i] * invSw);
        g_mug[b][i] = (float)(sg[i] * invSw);
    }

    // Analytic part of bond numerator: sum_ij wi wj (dp^2 + dg^2)
    g_analytic[b] = 2.0 * Sw * (g_Spp[b] + g_Sgg[b])
                  - 2.0 * (sp[0]*sp[0] + sp[1]*sp[1] + sp[2]*sp[2]
                         + sg[0]*sg[0] + sg[1]*sg[1] + sg[2]*sg[2]);
}

// ---------------- Kernel C: point loss sum w * ||p - (R(g-mug) + mup)|| ----------------
// grid: (chunks, B)
__global__ void pts_kernel(const float* __restrict__ p, const float* __restrict__ gt,
                           const float* __restrict__ w, int N) {
    int b = blockIdx.y;
    int i0 = blockIdx.x * blockDim.x;
    const float* pb = p  + (size_t)b * N * 3;
    const float* gb = gt + (size_t)b * N * 3;
    const float* wb = w  + (size_t)b * N;

    float r00 = g_R[b][0], r01 = g_R[b][1], r02 = g_R[b][2];
    float r10 = g_R[b][3], r11 = g_R[b][4], r12 = g_R[b][5];
    float r20 = g_R[b][6], r21 = g_R[b][7], r22 = g_R[b][8];
    float m0 = g_mup[b][0], m1 = g_mup[b][1], m2 = g_mup[b][2];
    float u0 = g_mug[b][0], u1 = g_mug[b][1], u2 = g_mug[b][2];

    float acc = 0.0f;
    int i = i0 + threadIdx.x;
    if (i < N) {
        float gx = gb[3*i]   - u0;
        float gy = gb[3*i+1] - u1;
        float gz = gb[3*i+2] - u2;
        float ax = fmaf(r00, gx, fmaf(r01, gy, r02*gz)) + m0;
        float ay = fmaf(r10, gx, fmaf(r11, gy, r12*gz)) + m1;
        float az = fmaf(r20, gx, fmaf(r21, gy, r22*gz)) + m2;
        float dx = pb[3*i]   - ax;
        float dy = pb[3*i+1] - ay;
        float dz = pb[3*i+2] - az;
        float nsq = fmaf(dx, dx, fmaf(dy, dy, dz*dz));
        acc = wb[i] * fsqrt_fast(nsq);
    }
    float tot = block_reduce_f(acc);
    if (threadIdx.x == 0) atomicAdd(&g_losspts, (double)tot);
}

// ---------------- Kernel D: bond cross term sum_ij wi wj * dp * dg ----------------
// Triangular tiling: symmetric sum; off-diagonal tiles counted twice, diagonal once
// (diagonal pairs i==j contribute 0). grid: (tiles*(tiles+1)/2, B).
__global__ void bond_kernel(const float* __restrict__ p, const float* __restrict__ gt,
                            const float* __restrict__ w, int N) {
    __shared__ float4 shp[JT];
    __shared__ float4 shg[JT];

    int b = blockIdx.y;
    int k = blockIdx.x;
    int ti = 0;
    while ((ti + 1) * (ti + 2) / 2 <= k) ti++;   // uniform across block
    int tj = k - ti * (ti + 1) / 2;
    float factor = (ti == tj) ? 1.0f : 2.0f;

    int j0 = tj * JT;
    int i  = ti * JT + threadIdx.x;
    const size_t base = (size_t)b * N;

    int j = j0 + threadIdx.x;
    if (j < N) {
        const float* pj = p  + (base + j) * 3;
        const float* gj = gt + (base + j) * 3;
        shp[threadIdx.x] = make_float4(pj[0], pj[1], pj[2], w[base + j]);
        shg[threadIdx.x] = make_float4(gj[0], gj[1], gj[2], 0.0f);
    } else {
        shp[threadIdx.x] = make_float4(0.f, 0.f, 0.f, 0.f);  // w=0 -> no contribution
        shg[threadIdx.x] = make_float4(0.f, 0.f, 0.f, 0.f);
    }
    __syncthreads();

    float xi = 0.f, yi = 0.f, zi = 0.f, gxi = 0.f, gyi = 0.f, gzi = 0.f, wi = 0.f;
    if (i < N) {
        const float* pi = p  + (base + i) * 3;
        const float* gi = gt + (base + i) * 3;
        xi = pi[0]; yi = pi[1]; zi = pi[2];
        gxi = gi[0]; gyi = gi[1]; gzi = gi[2];
        wi = w[base + i];
    }

    float acc = 0.0f;
    #pragma unroll 8
    for (int jj = 0; jj < JT; jj++) {
        float4 P = shp[jj];
        float4 G = shg[jj];
        float dx = xi - P.x, dy = yi - P.y, dz = zi - P.z;
        float dp2 = fmaf(dx, dx, fmaf(dy, dy, dz*dz));
        float ex = gxi - G.x, ey = gyi - G.y, ez = gzi - G.z;
        float dg2 = fmaf(ex, ex, fmaf(ey, ey, ez*ez));
        float s = fsqrt_fast(dp2 * dg2);   // dp*dg with ONE sqrt
        acc = fmaf(P.w, s, acc);
    }
    acc *= wi * factor;

    float tot = block_reduce_f(acc);
    if (threadIdx.x == 0) atomicAdd(&g_cross, (double)tot);
}

// ---------------- Kernel E: finalize ----------------
__global__ void final_kernel(const float* __restrict__ ht, float* __restrict__ out,
                             int B, int outn) {
    __shared__ double loss_sh;
    if (threadIdx.x == 0) {
        double totW = 0.0, den = 0.0, an = 0.0;
        for (int b = 0; b < B; b++) {
            double s = g_Sw[b];
            totW += s;
            den  += s * s;
            an   += g_analytic[b];
        }
        double loss_pts  = g_losspts / totW;
        double loss_bond = (an - 2.0 * g_cross) / den;
        loss_sh = loss_pts + 1.0 * loss_bond;   // ALPHA_BOND = 1
    }
    __syncthreads();
    int b = threadIdx.x;
    if (b < outn && b < B) {
        double h = (double)ht[b];
        out[b] = (float)((h*h + 256.0) / ((h + 16.0)*(h + 16.0)) * loss_sh);
    }
}

// ---------------- launcher ----------------
extern "C" void kernel_launch(void* const* d_in, const int* in_sizes, int n_in,
                              void* d_out, int out_size) {
    const float* p  = (const float*)d_in[0];  // xpred_l [B,N,3]
    const float* g  = (const float*)d_in[1];  // xGT_l   [B,N,3]
    const float* ht = (const float*)d_in[2];  // ht      [B]
    const float* w  = (const float*)d_in[3];  // w_l     [B,N]

    int B = in_sizes[2];
    if (B > MAXB) B = MAXB;
    int N = in_sizes[3] / B;

    reduce_kernel<<<B, 256>>>(p, g, w, N);
    solve_kernel<<<1, 32>>>(B);

    int chunks = (N + 255) / 256;
    pts_kernel<<<dim3(chunks, B), 256>>>(p, g, w, N);

    int tiles = (N + JT - 1) / JT;
    dim3 gridD(tiles * (tiles + 1) / 2, B);
    bond_kernel<<<gridD, JT>>>(p, g, w, N);

    final_kernel<<<1, 32>>>(ht, (float*)d_out, B, out_size);
}

// round 4
// speedup vs baseline: 3.8013x; 1.0703x over previous
#include <cuda_runtime.h>
#include <cstdint>

#define MAXB 8
#define JT 128
#define MAXTILES 40
#define MAXTRI (MAXTILES * (MAXTILES + 1) / 2)   // 820

// ---------------- scratch (device globals; no allocation) ----------------
__device__ float  g_mom_part[MAXB][MAXTILES][18]; // per-diagonal-tile moment partials
__device__ float  g_cross_part[MAXB * MAXTRI];    // per-block bond cross partials
__device__ float  g_pts_part[MAXB * 64];          // per-block point-loss partials
__device__ double g_Sw[MAXB];
__device__ double g_analytic[MAXB];
__device__ float  g_R[MAXB][9];
__device__ float  g_mup[MAXB][3];
__device__ float  g_mug[MAXB][3];
__device__ int    g_count = 0;                    // last-block counter (self-resetting)

__device__ __forceinline__ float fsqrt_fast(float x) {
    float r; asm("sqrt.approx.f32 %0, %1;" : "=f"(r) : "f"(x)); return r;
}

__device__ __forceinline__ float block_reduce_f(float v) {
    #pragma unroll
    for (int o = 16; o > 0; o >>= 1) v += __shfl_down_sync(0xffffffffu, v, o);
    __shared__ float s[32];
    int lane = threadIdx.x & 31, wid = threadIdx.x >> 5;
    if (lane == 0) s[wid] = v;
    __syncthreads();
    int nw = (blockDim.x + 31) >> 5;
    v = (threadIdx.x < nw) ? s[threadIdx.x] : 0.0f;
    if (wid == 0) {
        #pragma unroll
        for (int o = 16; o > 0; o >>= 1) v += __shfl_down_sync(0xffffffffu, v, o);
    }
    return v;  // valid in thread 0
}

// ---------------- Kernel 1: bond cross term + (on diagonal tiles) moments ----------------
// Triangular tiling over JT x JT tiles; off-diagonal tiles counted twice (symmetric sum,
// i==j pairs contribute 0). grid: (tiles*(tiles+1)/2, B), block: JT threads.
__global__ void bond_kernel(const float* __restrict__ p, const float* __restrict__ gt,
                            const float* __restrict__ w, int N, int ntri) {
    __shared__ float4 shp[JT];
    __shared__ float4 shg[JT];
    __shared__ float  smom[4][18];

    int b = blockIdx.y;
    int k = blockIdx.x;
    // decode triangular index (k uniform per block)
    int ti = (int)((__fsqrt_rn(8.0f * (float)k + 1.0f) - 1.0f) * 0.5f);
    while ((ti + 1) * (ti + 2) / 2 <= k) ti++;
    while (ti * (ti + 1) / 2 > k) ti--;
    int tj = k - ti * (ti + 1) / 2;

    const size_t base = (size_t)b * N;
    int tid = threadIdx.x;

    int j = tj * JT + tid;
    if (j < N) {
        const float* pj = p  + (base + j) * 3;
        const float* gj = gt + (base + j) * 3;
        shp[tid] = make_float4(pj[0], pj[1], pj[2], w[base + j]);
        shg[tid] = make_float4(gj[0], gj[1], gj[2], 0.0f);
    } else {
        shp[tid] = make_float4(0.f, 0.f, 0.f, 0.f);  // w=0 -> no contribution
        shg[tid] = make_float4(0.f, 0.f, 0.f, 0.f);
    }
    __syncthreads();

    int i = ti * JT + tid;
    float xi = 0.f, yi = 0.f, zi = 0.f, gxi = 0.f, gyi = 0.f, gzi = 0.f, wi = 0.f;
    if (i < N) {
        const float* pi = p  + (base + i) * 3;
        const float* gi = gt + (base + i) * 3;
        xi = pi[0]; yi = pi[1]; zi = pi[2];
        gxi = gi[0]; gyi = gi[1]; gzi = gi[2];
        wi = w[base + i];
    }

    float acc = 0.0f;
    #pragma unroll 8
    for (int jj = 0; jj < JT; jj++) {
        float4 P = shp[jj];
        float4 G = shg[jj];
        float dx = xi - P.x, dy = yi - P.y, dz = zi - P.z;
        float dp2 = fmaf(dx, dx, fmaf(dy, dy, dz * dz));
        float ex = gxi - G.x, ey = gyi - G.y, ez = gzi - G.z;
        float dg2 = fmaf(ex, ex, fmaf(ey, ey, ez * ez));
        float s = fsqrt_fast(dp2 * dg2);   // dp*dg with ONE sqrt
        acc = fmaf(P.w, s, acc);
    }
    float factor = (ti == tj) ? 1.0f : 2.0f;
    acc *= wi * factor;

    float tot = block_reduce_f(acc);
    if (tid == 0) g_cross_part[b * ntri + k] = tot;

    // Diagonal tiles also compute the 18 weighted moments for their i-range
    // (one point per thread, already resident in registers).
    if (ti == tj) {
        float m[18];
        float wpx = wi * xi, wpy = wi * yi, wpz = wi * zi;
        m[0]  = wi;
        m[1]  = wpx; m[2]  = wpy; m[3]  = wpz;
        m[4]  = wi * gxi; m[5]  = wi * gyi; m[6]  = wi * gzi;
        m[7]  = wpx * gxi; m[8]  = wpx * gyi; m[9]  = wpx * gzi;
        m[10] = wpy * gxi; m[11] = wpy * gyi; m[12] = wpy * gzi;
        m[13] = wpz * gxi; m[14] = wpz * gyi; m[15] = wpz * gzi;
        m[16] = fmaf(wpx, xi, fmaf(wpy, yi, wpz * zi));
        m[17] = wi * fmaf(gxi, gxi, fmaf(gyi, gyi, gzi * gzi));

        #pragma unroll
        for (int kk = 0; kk < 18; kk++) {
            #pragma unroll
            for (int o = 16; o > 0; o >>= 1)
                m[kk] += __shfl_down_sync(0xffffffffu, m[kk], o);
        }
        int lane = tid & 31, wid = tid >> 5;
        if (lane == 0) {
            #pragma unroll
            for (int kk = 0; kk < 18; kk++) smom[wid][kk] = m[kk];
        }
        __syncthreads();
        if (tid < 18)
            g_mom_part[b][ti][tid] =
                smom[0][tid] + smom[1][tid] + smom[2][tid] + smom[3][tid];
    }
}

// ---------------- Kernel 2: moment combine (double) + Kabsch solve (float Jacobi) ----------------
__global__ void solve_kernel(int B, int tiles) {
    __shared__ double S[MAXB][18];
    int t = threadIdx.x;
    if (t < B * 18) {
        int bb = t / 18, kk = t % 18;
        double v = 0.0;
        for (int tt = 0; tt < tiles; tt++) v += (double)g_mom_part[bb][tt][kk];
        S[bb][kk] = v;
    }
    __syncthreads();

    int b = t;
    if (b >= B) return;

    double Sw = S[b][0];
    double invSw = 1.0 / Sw;
    double sp[3] = { S[b][1], S[b][2], S[b][3] };
    double sg[3] = { S[b][4], S[b][5], S[b][6] };

    // Centered cross-covariance in double (cancellation-sensitive step)
    double Md[3][3];
    #pragma unroll
    for (int i = 0; i < 3; i++)
        #pragma unroll
        for (int j = 0; j < 3; j++)
            Md[i][j] = S[b][7 + i * 3 + j] - sp[i] * sg[j] * invSw;

    // Scale-normalize and drop to float
    double mx = 0.0;
    #pragma unroll
    for (int i = 0; i < 3; i++)
        #pragma unroll
        for (int j = 0; j < 3; j++)
            mx = fmax(mx, fabs(Md[i][j]));
    double invmx = (mx > 0.0) ? 1.0 / mx : 0.0;

    float M[3][3];
    #pragma unroll
    for (int i = 0; i < 3; i++)
        #pragma unroll
        for (int j = 0; j < 3; j++)
            M[i][j] = (float)(Md[i][j] * invmx);

    // A = M^T M (symmetric PSD, entries O(1))
    float A[3][3];
    #pragma unroll
    for (int i = 0; i < 3; i++)
        #pragma unroll
        for (int j = 0; j < 3; j++)
            A[i][j] = M[0][i] * M[0][j] + M[1][i] * M[1][j] + M[2][i] * M[2][j];

    float V[3][3] = {{1, 0, 0}, {0, 1, 0}, {0, 0, 1}};

    // Cyclic Jacobi in float (fixed count -> deterministic)
    for (int sweep = 0; sweep < 12; sweep++) {
        #pragma unroll
        for (int pair = 0; pair < 3; pair++) {
            int pp = (pair == 2) ? 1 : 0;
            int qq = (pair == 0) ? 1 : 2;
            float apq = A[pp][qq];
            if (fabsf(apq) < 1e-20f) continue;
            float theta = (A[qq][qq] - A[pp][pp]) / (2.0f * apq);
            float tt = ((theta >= 0.0f) ? 1.0f : -1.0f) /
                       (fabsf(theta) + fsqrt_fast(fmaf(theta, theta, 1.0f)));
            float c = rsqrtf(fmaf(tt, tt, 1.0f));
            float s = tt * c;
            float app = A[pp][pp], aq2 = A[qq][qq];
            A[pp][pp] = app - tt * apq;
            A[qq][qq] = aq2 + tt * apq;
            A[pp][qq] = A[qq][pp] = 0.0f;
            int r = 3 - pp - qq;
            float arp = A[r][pp], arq = A[r][qq];
            A[r][pp] = A[pp][r] = c * arp - s * arq;
            A[r][qq] = A[qq][r] = s * arp + c * arq;
            #pragma unroll
            for (int kk = 0; kk < 3; kk++) {
                float vkp = V[kk][pp], vkq = V[kk][qq];
                V[kk][pp] = c * vkp - s * vkq;
                V[kk][qq] = s * vkp + c * vkq;
            }
        }
    }

    // Sort eigenvalues descending
    float lam[3] = { A[0][0], A[1][1], A[2][2] };
    int id[3] = {0, 1, 2};
    if (lam[id[0]] < lam[id[1]]) { int x = id[0]; id[0] = id[1]; id[1] = x; }
    if (lam[id[0]] < lam[id[2]]) { int x = id[0]; id[0] = id[2]; id[2] = x; }
    if (lam[id[1]] < lam[id[2]]) { int x = id[1]; id[1] = id[2]; id[2] = x; }

    // U columns: u_k = normalize(M v_k) for k=0,1; u_2 = u_0 x u_1 (det flip absorbed)
    float U[3][3];
    #pragma unroll
    for (int kk = 0; kk < 2; kk++) {
        float v0 = V[0][id[kk]], v1 = V[1][id[kk]], v2 = V[2][id[kk]];
        float u0 = M[0][0] * v0 + M[0][1] * v1 + M[0][2] * v2;
        float u1 = M[1][0] * v0 + M[1][1] * v1 + M[1][2] * v2;
        float u2 = M[2][0] * v0 + M[2][1] * v1 + M[2][2] * v2;
        float inv = rsqrtf(fmaxf(u0 * u0 + u1 * u1 + u2 * u2, 1e-30f));
        U[0][kk] = u0 * inv; U[1][kk] = u1 * inv; U[2][kk] = u2 * inv;
    }
    U[0][2] = U[1][0] * U[2][1] - U[2][0] * U[1][1];
    U[1][2] = U[2][0] * U[0][1] - U[0][0] * U[2][1];
    U[2][2] = U[0][0] * U[1][1] - U[1][0] * U[0][1];

    #pragma unroll
    for (int i = 0; i < 3; i++)
        #pragma unroll
        for (int j = 0; j < 3; j++)
            g_R[b][i * 3 + j] = U[i][0] * V[j][id[0]] + U[i][1] * V[j][id[1]] + U[i][2] * V[j][id[2]];

    #pragma unroll
    for (int i = 0; i < 3; i++) {
        g_mup[b][i] = (float)(sp[i] * invSw);
        g_mug[b][i] = (float)(sg[i] * invSw);
    }

    g_Sw[b] = Sw;
    // Analytic part of bond numerator: sum_ij wi wj (dp^2 + dg^2)
    g_analytic[b] = 2.0 * Sw * (S[b][16] + S[b][17])
                  - 2.0 * (sp[0] * sp[0] + sp[1] * sp[1] + sp[2] * sp[2]
                         + sg[0] * sg[0] + sg[1] * sg[1] + sg[2] * sg[2]);
}

// ---------------- Kernel 3: point loss + final combine (last-block pattern) ----------------
// grid: (chunks, B), block: 256
__global__ void pts_final_kernel(const float* __restrict__ p, const float* __restrict__ gt,
                                 const float* __restrict__ w, const float* __restrict__ ht,
                                 float* __restrict__ out, int N, int B, int ntri, int outn) {
    int b = blockIdx.y;
    const float* pb = p  + (size_t)b * N * 3;
    const float* gb = gt + (size_t)b * N * 3;
    const float* wb = w  + (size_t)b * N;

    float r00 = g_R[b][0], r01 = g_R[b][1], r02 = g_R[b][2];
    float r10 = g_R[b][3], r11 = g_R[b][4], r12 = g_R[b][5];
    float r20 = g_R[b][6], r21 = g_R[b][7], r22 = g_R[b][8];
    float m0 = g_mup[b][0], m1 = g_mup[b][1], m2 = g_mup[b][2];
    float u0 = g_mug[b][0], u1 = g_mug[b][1], u2 = g_mug[b][2];

    float acc = 0.0f;
    int i = blockIdx.x * blockDim.x + threadIdx.x;
    if (i < N) {
        float gx = gb[3 * i]     - u0;
        float gy = gb[3 * i + 1] - u1;
        float gz = gb[3 * i + 2] - u2;
        float ax = fmaf(r00, gx, fmaf(r01, gy, r02 * gz)) + m0;
        float ay = fmaf(r10, gx, fmaf(r11, gy, r12 * gz)) + m1;
        float az = fmaf(r20, gx, fmaf(r21, gy, r22 * gz)) + m2;
        float dx = pb[3 * i]     - ax;
        float dy = pb[3 * i + 1] - ay;
        float dz = pb[3 * i + 2] - az;
        float nsq = fmaf(dx, dx, fmaf(dy, dy, dz * dz));
        acc = wb[i] * fsqrt_fast(nsq);
    }
    float tot = block_reduce_f(acc);

    __shared__ int isLast;
    int nblocks = gridDim.x * gridDim.y;
    if (threadIdx.x == 0) {
        g_pts_part[b * gridDim.x + blockIdx.x] = tot;
        __threadfence();
        int old = atomicAdd(&g_count, 1);
        isLast = (old == nblocks - 1) ? 1 : 0;
    }
    __syncthreads();
    if (!isLast) return;

    // ---- final combine (executed by exactly one block; fixed summation order) ----
    int ncross = B * ntri;
    double vp = 0.0, vc = 0.0;
    for (int idx = threadIdx.x; idx < nblocks; idx += blockDim.x) vp += (double)g_pts_part[idx];
    for (int idx = threadIdx.x; idx < ncross;  idx += blockDim.x) vc += (double)g_cross_part[idx];

    __shared__ double rp[256];
    __shared__ double rc[256];
    rp[threadIdx.x] = vp;
    rc[threadIdx.x] = vc;
    __syncthreads();
    for (int off = 128; off > 0; off >>= 1) {
        if (threadIdx.x < off) {
            rp[threadIdx.x] += rp[threadIdx.x + off];
            rc[threadIdx.x] += rc[threadIdx.x + off];
        }
        __syncthreads();
    }

    __shared__ double loss_sh;
    if (threadIdx.x == 0) {
        double totW = 0.0, den = 0.0, an = 0.0;
        for (int bb = 0; bb < B; bb++) {
            double s = g_Sw[bb];
            totW += s;
            den  += s * s;
            an   += g_analytic[bb];
        }
        double loss_pts  = rp[0] / totW;
        double loss_bond = (an - 2.0 * rc[0]) / den;
        loss_sh = loss_pts + 1.0 * loss_bond;   // ALPHA_BOND = 1
        g_count = 0;                            // self-reset for next replay
    }
    __syncthreads();
    int bb = threadIdx.x;
    if (bb < outn && bb < B) {
        double h = (double)ht[bb];
        out[bb] = (float)((h * h + 256.0) / ((h + 16.0) * (h + 16.0)) * loss_sh);
    }
}

// ---------------- launcher ----------------
extern "C" void kernel_launch(void* const* d_in, const int* in_sizes, int n_in,
                              void* d_out, int out_size) {
    const float* p  = (const float*)d_in[0];  // xpred_l [B,N,3]
    const float* g  = (const float*)d_in[1];  // xGT_l   [B,N,3]
    const float* ht = (const float*)d_in[2];  // ht      [B]
    const float* w  = (const float*)d_in[3];  // w_l     [B,N]

    int B = in_sizes[2];
    if (B > MAXB) B = MAXB;
    int N = in_sizes[3] / B;

    int tiles = (N + JT - 1) / JT;
    if (tiles > MAXTILES) tiles = MAXTILES;   // (inputs are B=4, N=2048 -> 16 tiles)
    int ntri = tiles * (tiles + 1) / 2;

    bond_kernel<<<dim3(ntri, B), JT>>>(p, g, w, N, ntri);
    solve_kernel<<<1, 160>>>(B, tiles);

    int chunks = (N + 255) / 256;
    pts_final_kernel<<<dim3(chunks, B), 256>>>(p, g, w, ht, (float*)d_out,
                                               N, B, ntri, out_size);
}

// round 6
// speedup vs baseline: 3.8350x; 1.0089x over previous
#include <cuda_runtime.h>
#include <cstdint>

#define MAXB 8
#define JT 128
#define SPLIT 2
#define JH (JT / SPLIT)
#define MAXTILES 40
#define MAXTRI (MAXTILES * (MAXTILES + 1) / 2)   // 820

// ---------------- scratch (device globals; no allocation) ----------------
__device__ float  g_mom_part[MAXB][MAXTILES][18];       // per-diagonal-tile moment partials
__device__ float  g_cross_part[MAXB * MAXTRI * SPLIT];  // per-block bond cross partials
__device__ float  g_pts_part[MAXB * 64];                // per-block point-loss partials
__device__ double g_Sw[MAXB];
__device__ double g_analytic[MAXB];
__device__ float  g_R[MAXB][9];
__device__ float  g_mup[MAXB][3];
__device__ float  g_mug[MAXB][3];
__device__ int    g_count = 0;                          // last-block counter (self-resetting)

__device__ __forceinline__ float fsqrt_fast(float x) {
    float r; asm("sqrt.approx.f32 %0, %1;" : "=f"(r) : "f"(x)); return r;
}

__device__ __forceinline__ float block_reduce_f(float v) {
    #pragma unroll
    for (int o = 16; o > 0; o >>= 1) v += __shfl_down_sync(0xffffffffu, v, o);
    __shared__ float s[32];
    int lane = threadIdx.x & 31, wid = threadIdx.x >> 5;
    if (lane == 0) s[wid] = v;
    __syncthreads();
    int nw = (blockDim.x + 31) >> 5;
    v = (threadIdx.x < nw) ? s[threadIdx.x] : 0.0f;
    if (wid == 0) {
        #pragma unroll
        for (int o = 16; o > 0; o >>= 1) v += __shfl_down_sync(0xffffffffu, v, o);
    }
    return v;  // valid in thread 0
}

// ---------------- Kernel 1: bond cross term + (on diagonal tiles) moments ----------------
// Triangular JTxJT tiles, each split into SPLIT j-halves for occupancy.
// grid: (tiles*(tiles+1)/2, SPLIT, B), block: JT threads, each owns one i.
// Inner math uses dp^2 = |pi|^2 + |pj|^2 - 2 pi.pj  (10 FMA-pipe ops/pair).
__global__ void __launch_bounds__(JT) bond_kernel(
        const float* __restrict__ p, const float* __restrict__ gt,
        const float* __restrict__ w, int N, int ntri) {
    __shared__ float4 shP[JH];   // (-2px, -2py, -2pz, |pj|^2)
    __shared__ float4 shG[JH];   // (-2gx, -2gy, -2gz, |gj|^2)
    __shared__ float  shW[JH];   // wj
    __shared__ float  smom[4][18];

    int b   = blockIdx.z;
    int sub = blockIdx.y;
    int k   = blockIdx.x;
    // decode triangular index (k uniform per block)
    int ti = (int)((__fsqrt_rn(8.0f * (float)k + 1.0f) - 1.0f) * 0.5f);
    while ((ti + 1) * (ti + 2) / 2 <= k) ti++;
    while (ti * (ti + 1) / 2 > k) ti--;
    int tj = k - ti * (ti + 1) / 2;

    const size_t base = (size_t)b * N;
    int tid = threadIdx.x;

    // load the 64-j half-tile into shared (threads 0-63: p+w, threads 64-127: g)
    int jl = tid & (JH - 1);
    int j  = tj * JT + sub * JH + jl;
    if (tid < JH) {
        if (j < N) {
            const float* pj = p + (base + j) * 3;
            float px = pj[0], py = pj[1], pz = pj[2];
            shP[jl] = make_float4(-2.0f * px, -2.0f * py, -2.0f * pz,
                                  fmaf(px, px, fmaf(py, py, pz * pz)));
            shW[jl] = w[base + j];
        } else {
            shP[jl] = make_float4(0.f, 0.f, 0.f, 0.f);
            shW[jl] = 0.f;                       // w=0 -> no contribution
        }
    } else {
        if (j < N) {
            const float* gj = gt + (base + j) * 3;
            float gx = gj[0], gy = gj[1], gz = gj[2];
            shG[jl] = make_float4(-2.0f * gx, -2.0f * gy, -2.0f * gz,
                                  fmaf(gx, gx, fmaf(gy, gy, gz * gz)));
        } else {
            shG[jl] = make_float4(0.f, 0.f, 0.f, 0.f);
        }
    }

    int i = ti * JT + tid;
    float xi = 0.f, yi = 0.f, zi = 0.f, gxi = 0.f, gyi = 0.f, gzi = 0.f, wi = 0.f;
    if (i < N) {
        const float* pi = p  + (base + i) * 3;
        const float* gi = gt + (base + i) * 3;
        xi = pi[0]; yi = pi[1]; zi = pi[2];
        gxi = gi[0]; gyi = gi[1]; gzi = gi[2];
        wi = w[base + i];
    }
    float spi = fmaf(xi, xi, fmaf(yi, yi, zi * zi));
    float sgi = fmaf(gxi, gxi, fmaf(gyi, gyi, gzi * gzi));
    __syncthreads();

    float acc0 = 0.0f, acc1 = 0.0f;
    #pragma unroll 16
    for (int jj = 0; jj < JH; jj++) {
        float4 P = shP[jj];
        float4 G = shG[jj];
        float wj = shW[jj];
        float dp2 = fmaf(P.x, xi, spi + P.w);
        dp2 = fmaf(P.y, yi, dp2);
        dp2 = fmaf(P.z, zi, dp2);
        float dg2 = fmaf(G.x, gxi, sgi + G.w);
        dg2 = fmaf(G.y, gyi, dg2);
        dg2 = fmaf(G.z, gzi, dg2);
        float prod = fmaxf(dp2 * dg2, 0.0f);     // clamp fp cancellation
        float s = fsqrt_fast(prod);              // dp*dg with ONE sqrt
        if (jj & 1) acc1 = fmaf(wj, s, acc1);
        else        acc0 = fmaf(wj, s, acc0);
    }
    float factor = (ti == tj) ? 1.0f : 2.0f;
    float acc = (acc0 + acc1) * (wi * factor);

    float tot = block_reduce_f(acc);
    if (tid == 0) g_cross_part[(b * ntri + k) * SPLIT + sub] = tot;

    // Diagonal tiles (one split only) also compute the 18 weighted moments for
    // their i-range (one point per thread, already resident in registers).
    if (ti == tj && sub == 0) {
        float m[18];
        float wpx = wi * xi, wpy = wi * yi, wpz = wi * zi;
        m[0]  = wi;
        m[1]  = wpx; m[2]  = wpy; m[3]  = wpz;
        m[4]  = wi * gxi; m[5]  = wi * gyi; m[6]  = wi * gzi;
        m[7]  = wpx * gxi; m[8]  = wpx * gyi; m[9]  = wpx * gzi;
        m[10] = wpy * gxi; m[11] = wpy * gyi; m[12] = wpy * gzi;
        m[13] = wpz * gxi; m[14] = wpz * gyi; m[15] = wpz * gzi;
        m[16] = wi * spi;
        m[17] = wi * sgi;

        #pragma unroll
        for (int kk = 0; kk < 18; kk++) {
            #pragma unroll
            for (int o = 16; o > 0; o >>= 1)
                m[kk] += __shfl_down_sync(0xffffffffu, m[kk], o);
        }
        int lane = tid & 31, wid = tid >> 5;
        if (lane == 0) {
            #pragma unroll
            for (int kk = 0; kk < 18; kk++) smom[wid][kk] = m[kk];
        }
        __syncthreads();
        if (tid < 18)
            g_mom_part[b][ti][tid] =
                smom[0][tid] + smom[1][tid] + smom[2][tid] + smom[3][tid];
    }
}

// ---------------- Kernel 2: moment combine (double) + Kabsch solve (float Jacobi) ----------------
__global__ void solve_kernel(int B, int tiles) {
    __shared__ double S[MAXB][18];
    int t = threadIdx.x;
    if (t < B * 18) {
        int bb = t / 18, kk = t % 18;
        double v = 0.0;
        for (int tt = 0; tt < tiles; tt++) v += (double)g_mom_part[bb][tt][kk];
        S[bb][kk] = v;
    }
    __syncthreads();

    int b = t;
    if (b >= B) return;

    double Sw = S[b][0];
    double invSw = 1.0 / Sw;
    double sp[3] = { S[b][1], S[b][2], S[b][3] };
    double sg[3] = { S[b][4], S[b][5], S[b][6] };

    // Centered cross-covariance in double (cancellation-sensitive step)
    double Md[3][3];
    #pragma unroll
    for (int i = 0; i < 3; i++)
        #pragma unroll
        for (int j = 0; j < 3; j++)
            Md[i][j] = S[b][7 + i * 3 + j] - sp[i] * sg[j] * invSw;

    // Scale-normalize and drop to float
    double mx = 0.0;
    #pragma unroll
    for (int i = 0; i < 3; i++)
        #pragma unroll
        for (int j = 0; j < 3; j++)
            mx = fmax(mx, fabs(Md[i][j]));
    double invmx = (mx > 0.0) ? 1.0 / mx : 0.0;

    float M[3][3];
    #pragma unroll
    for (int i = 0; i < 3; i++)
        #pragma unroll
        for (int j = 0; j < 3; j++)
            M[i][j] = (float)(Md[i][j] * invmx);

    // A = M^T M (symmetric PSD, entries O(1))
    float A[3][3];
    #pragma unroll
    for (int i = 0; i < 3; i++)
        #pragma unroll
        for (int j = 0; j < 3; j++)
            A[i][j] = M[0][i] * M[0][j] + M[1][i] * M[1][j] + M[2][i] * M[2][j];

    float V[3][3] = {{1, 0, 0}, {0, 1, 0}, {0, 0, 1}};

    // Cyclic Jacobi in float (fixed count -> deterministic)
    for (int sweep = 0; sweep < 12; sweep++) {
        #pragma unroll
        for (int pair = 0; pair < 3; pair++) {
            int pp = (pair == 2) ? 1 : 0;
            int qq = (pair == 0) ? 1 : 2;
            float apq = A[pp][qq];
            if (fabsf(apq) < 1e-20f) continue;
            float theta = (A[qq][qq] - A[pp][pp]) / (2.0f * apq);
            float tt = ((theta >= 0.0f) ? 1.0f : -1.0f) /
                       (fabsf(theta) + fsqrt_fast(fmaf(theta, theta, 1.0f)));
            float c = rsqrtf(fmaf(tt, tt, 1.0f));
            float s = tt * c;
            float app = A[pp][pp], aq2 = A[qq][qq];
            A[pp][pp] = app - tt * apq;
            A[qq][qq] = aq2 + tt * apq;
            A[pp][qq] = A[qq][pp] = 0.0f;
            int r = 3 - pp - qq;
            float arp = A[r][pp], arq = A[r][qq];
            A[r][pp] = A[pp][r] = c * arp - s * arq;
            A[r][qq] = A[qq][r] = s * arp + c * arq;
            #pragma unroll
            for (int kk = 0; kk < 3; kk++) {
                float vkp = V[kk][pp], vkq = V[kk][qq];
                V[kk][pp] = c * vkp - s * vkq;
                V[kk][qq] = s * vkp + c * vkq;
            }
        }
    }

    // Sort eigenvalues descending
    float lam[3] = { A[0][0], A[1][1], A[2][2] };
    int id[3] = {0, 1, 2};
    if (lam[id[0]] < lam[id[1]]) { int x = id[0]; id[0] = id[1]; id[1] = x; }
    if (lam[id[0]] < lam[id[2]]) { int x = id[0]; id[0] = id[2]; id[2] = x; }
    if (lam[id[1]] < lam[id[2]]) { int x = id[1]; id[1] = id[2]; id[2] = x; }

    // U columns: u_k = normalize(M v_k) for k=0,1; u_2 = u_0 x u_1 (det flip absorbed)
    float U[3][3];
    #pragma unroll
    for (int kk = 0; kk < 2; kk++) {
        float v0 = V[0][id[kk]], v1 = V[1][id[kk]], v2 = V[2][id[kk]];
        float u0 = M[0][0] * v0 + M[0][1] * v1 + M[0][2] * v2;
        float u1 = M[1][0] * v0 + M[1][1] * v1 + M[1][2] * v2;
        float u2 = M[2][0] * v0 + M[2][1] * v1 + M[2][2] * v2;
        float inv = rsqrtf(fmaxf(u0 * u0 + u1 * u1 + u2 * u2, 1e-30f));
        U[0][kk] = u0 * inv; U[1][kk] = u1 * inv; U[2][kk] = u2 * inv;
    }
    U[0][2] = U[1][0] * U[2][1] - U[2][0] * U[1][1];
    U[1][2] = U[2][0] * U[0][1] - U[0][0] * U[2][1];
    U[2][2] = U[0][0] * U[1][1] - U[1][0] * U[0][1];

    #pragma unroll
    for (int i = 0; i < 3; i++)
        #pragma unroll
        for (int j = 0; j < 3; j++)
            g_R[b][i * 3 + j] = U[i][0] * V[j][id[0]] + U[i][1] * V[j][id[1]] + U[i][2] * V[j][id[2]];

    #pragma unroll
    for (int i = 0; i < 3; i++) {
        g_mup[b][i] = (float)(sp[i] * invSw);
        g_mug[b][i] = (float)(sg[i] * invSw);
    }

    g_Sw[b] = Sw;
    // Analytic part of bond numerator: sum_ij wi wj (dp^2 + dg^2)
    g_analytic[b] = 2.0 * Sw * (S[b][16] + S[b][17])
                  - 2.0 * (sp[0] * sp[0] + sp[1] * sp[1] + sp[2] * sp[2]
                         + sg[0] * sg[0] + sg[1] * sg[1] + sg[2] * sg[2]);
}

// ---------------- Kernel 3: point loss + final combine (last-block pattern) ----------------
// grid: (chunks, B), block: 256
__global__ void pts_final_kernel(const float* __restrict__ p, const float* __restrict__ gt,
                                 const float* __restrict__ w, const float* __restrict__ ht,
                                 float* __restrict__ out, int N, int B, int ncross, int outn) {
    int b = blockIdx.y;
    const float* pb = p  + (size_t)b * N * 3;
    const float* gb = gt + (size_t)b * N * 3;
    const float* wb = w  + (size_t)b * N;

    float r00 = g_R[b][0], r01 = g_R[b][1], r02 = g_R[b][2];
    float r10 = g_R[b][3], r11 = g_R[b][4], r12 = g_R[b][5];
    float r20 = g_R[b][6], r21 = g_R[b][7], r22 = g_R[b][8];
    float m0 = g_mup[b][0], m1 = g_mup[b][1], m2 = g_mup[b][2];
    float u0 = g_mug[b][0], u1 = g_mug[b][1], u2 = g_mug[b][2];

    float acc = 0.0f;
    int i = blockIdx.x * blockDim.x + threadIdx.x;
    if (i < N) {
        float gx = gb[3 * i]     - u0;
        float gy = gb[3 * i + 1] - u1;
        float gz = gb[3 * i + 2] - u2;
        float ax = fmaf(r00, gx, fmaf(r01, gy, r02 * gz)) + m0;
        float ay = fmaf(r10, gx, fmaf(r11, gy, r12 * gz)) + m1;
        float az = fmaf(r20, gx, fmaf(r21, gy, r22 * gz)) + m2;
        float dx = pb[3 * i]     - ax;
        float dy = pb[3 * i + 1] - ay;
        float dz = pb[3 * i + 2] - az;
        float nsq = fmaf(dx, dx, fmaf(dy, dy, dz * dz));
        acc = wb[i] * fsqrt_fast(nsq);
    }
    float tot = block_reduce_f(acc);

    __shared__ int isLast;
    int nblocks = gridDim.x * gridDim.y;
    if (threadIdx.x == 0) {
        g_pts_part[b * gridDim.x + blockIdx.x] = tot;
        __threadfence();
        int old = atomicAdd(&g_count, 1);
        isLast = (old == nblocks - 1) ? 1 : 0;
    }
    __syncthreads();
    if (!isLast) return;

    // ---- final combine (executed by exactly one block; fixed summation order) ----
    double vp = 0.0, vc = 0.0;
    for (int idx = threadIdx.x; idx < nblocks; idx += blockDim.x) vp += (double)g_pts_part[idx];
    for (int idx = threadIdx.x; idx < ncross;  idx += blockDim.x) vc += (double)g_cross_part[idx];

    __shared__ double rp[256];
    __shared__ double rc[256];
    rp[threadIdx.x] = vp;
    rc[threadIdx.x] = vc;
    __syncthreads();
    for (int off = 128; off > 0; off >>= 1) {
        if (threadIdx.x < off) {
            rp[threadIdx.x] += rp[threadIdx.x + off];
            rc[threadIdx.x] += rc[threadIdx.x + off];
        }
        __syncthreads();
    }

    __shared__ double loss_sh;
    if (threadIdx.x == 0) {
        double totW = 0.0, den = 0.0, an = 0.0;
        for (int bb = 0; bb < B; bb++) {
            double s = g_Sw[bb];
            totW += s;
            den  += s * s;
            an   += g_analytic[bb];
        }
        double loss_pts  = rp[0] / totW;
        double loss_bond = (an - 2.0 * rc[0]) / den;
        loss_sh = loss_pts + 1.0 * loss_bond;   // ALPHA_BOND = 1
        g_count = 0;                            // self-reset for next replay
    }
    __syncthreads();
    int bb = threadIdx.x;
    if (bb < outn && bb < B) {
        double h = (double)ht[bb];
        out[bb] = (float)((h * h + 256.0) / ((h + 16.0) * (h + 16.0)) * loss_sh);
    }
}

// ---------------- launcher ----------------
extern "C" void kernel_launch(void* const* d_in, const int* in_sizes, int n_in,
                              void* d_out, int out_size) {
    const float* p  = (const float*)d_in[0];  // xpred_l [B,N,3]
    const float* g  = (const float*)d_in[1];  // xGT_l   [B,N,3]
    const float* ht = (const float*)d_in[2];  // ht      [B]
    const float* w  = (const float*)d_in[3];  // w_l     [B,N]

    int B = in_sizes[2];
    if (B > MAXB) B = MAXB;
    int N = in_sizes[3] / B;

    int tiles = (N + JT - 1) / JT;
    if (tiles > MAXTILES) tiles = MAXTILES;   // (inputs are B=4, N=2048 -> 16 tiles)
    int ntri = tiles * (tiles + 1) / 2;
    int ncross = B * ntri * SPLIT;

    bond_kernel<<<dim3(ntri, SPLIT, B), JT>>>(p, g, w, N, ntri);
    solve_kernel<<<1, 160>>>(B, tiles);

    int chunks = (N + 255) / 256;
    pts_final_kernel<<<dim3(chunks, B), 256>>>(p, g, w, ht, (float*)d_out,
                                               N, B, ncross, out_size);
}

// round 7
// speedup vs baseline: 4.0885x; 1.0661x over previous
#include <cuda_runtime.h>
#include <cstdint>

#define MAXB 8
#define JT 128
#define SPLIT 2
#define JH (JT / SPLIT)
#define JG (JH / 2)          // packed j-groups per block
#define MAXTILES 40
#define MAXTRI (MAXTILES * (MAXTILES + 1) / 2)   // 820

// ---------------- scratch (device globals; no allocation) ----------------
__device__ float  g_mom_part[MAXB][MAXTILES][18];       // per-diagonal-tile moment partials
__device__ float  g_cross_part[MAXB * MAXTRI * SPLIT];  // per-block bond cross partials
__device__ float  g_pts_part[MAXB * 64];                // per-block point-loss partials
__device__ double g_Sw[MAXB];
__device__ double g_analytic[MAXB];
__device__ float  g_R[MAXB][9];
__device__ float  g_mup[MAXB][3];
__device__ float  g_mug[MAXB][3];
__device__ int    g_count = 0;                          // last-block counter (self-resetting)

// ---- packed f32x2 helpers (sm_103a FFMA2 path; ptxas never auto-fuses) ----
#define FMA2(d, a, b, c) asm("fma.rn.f32x2 %0, %1, %2, %3;" : "=l"(d) : "l"(a), "l"(b), "l"(c))
#define ADD2(d, a, b)    asm("add.rn.f32x2 %0, %1, %2;"     : "=l"(d) : "l"(a), "l"(b))
#define MUL2(d, a, b)    asm("mul.rn.f32x2 %0, %1, %2;"     : "=l"(d) : "l"(a), "l"(b))

__device__ __forceinline__ unsigned long long packf2(float lo, float hi) {
    unsigned long long r;
    asm("mov.b64 %0, {%1, %2};" : "=l"(r) : "f"(lo), "f"(hi));
    return r;
}
__device__ __forceinline__ void unpackf2(float& lo, float& hi, unsigned long long v) {
    asm("mov.b64 {%0, %1}, %2;" : "=f"(lo), "=f"(hi) : "l"(v));
}

__device__ __forceinline__ float fsqrt_fast(float x) {
    float r; asm("sqrt.approx.f32 %0, %1;" : "=f"(r) : "f"(x)); return r;
}

__device__ __forceinline__ float block_reduce_f(float v) {
    #pragma unroll
    for (int o = 16; o > 0; o >>= 1) v += __shfl_down_sync(0xffffffffu, v, o);
    __shared__ float s[32];
    int lane = threadIdx.x & 31, wid = threadIdx.x >> 5;
    if (lane == 0) s[wid] = v;
    __syncthreads();
    int nw = (blockDim.x + 31) >> 5;
    v = (threadIdx.x < nw) ? s[threadIdx.x] : 0.0f;
    if (wid == 0) {
        #pragma unroll
        for (int o = 16; o > 0; o >>= 1) v += __shfl_down_sync(0xffffffffu, v, o);
    }
    return v;  // valid in thread 0
}

// ---------------- Kernel 1: bond cross term + (on diagonal tiles) moments ----------------
// Triangular JTxJT tiles, each split into SPLIT j-halves. Inner loop processes
// packed j-PAIRS with f32x2 FMA: dp^2 = |pi|^2 + |pj|^2 - 2 pi.pj per lane.
// grid: (tiles*(tiles+1)/2, SPLIT, B), block: JT threads, each owns one i.
__global__ void __launch_bounds__(JT) bond_kernel(
        const float* __restrict__ p, const float* __restrict__ gt,
        const float* __restrict__ w, int N, int ntri) {
    // packed-lane shared: group g covers j-pair (2g, 2g+1)
    __shared__ ulonglong2 shPa[JG];           // (px2, py2)   lanes = -2*p
    __shared__ ulonglong2 shPb[JG];           // (pz2, pw2)   pw = |p|^2
    __shared__ ulonglong2 shGa[JG];           // (gx2, gy2)   lanes = -2*g
    __shared__ ulonglong2 shGb[JG];           // (gz2, gw2)   gw = |g|^2
    __shared__ unsigned long long shw[JG];    // (w0, w1)
    __shared__ float smom[4][18];

    int b   = blockIdx.z;
    int sub = blockIdx.y;
    int k   = blockIdx.x;
    // decode triangular index (k uniform per block)
    int ti = (int)((__fsqrt_rn(8.0f * (float)k + 1.0f) - 1.0f) * 0.5f);
    while ((ti + 1) * (ti + 2) / 2 <= k) ti++;
    while (ti * (ti + 1) / 2 > k) ti--;
    int tj = k - ti * (ti + 1) / 2;

    const size_t base = (size_t)b * N;
    int tid = threadIdx.x;

    // ---- stage the 64-j half-tile as packed lanes (3 thread groups of 32) ----
    {
        int grp = tid & 31;
        int j0 = tj * JT + sub * JH + 2 * grp;
        int j1 = j0 + 1;
        if (tid < 32) {
            float x0 = 0.f, y0 = 0.f, z0 = 0.f, x1 = 0.f, y1 = 0.f, z1 = 0.f;
            if (j0 < N) { const float* q = p + (base + j0) * 3; x0 = q[0]; y0 = q[1]; z0 = q[2]; }
            if (j1 < N) { const float* q = p + (base + j1) * 3; x1 = q[0]; y1 = q[1]; z1 = q[2]; }
            float n0 = fmaf(x0, x0, fmaf(y0, y0, z0 * z0));
            float n1 = fmaf(x1, x1, fmaf(y1, y1, z1 * z1));
            shPa[grp] = make_ulonglong2(packf2(-2.f * x0, -2.f * x1),
                                        packf2(-2.f * y0, -2.f * y1));
            shPb[grp] = make_ulonglong2(packf2(-2.f * z0, -2.f * z1),
                                        packf2(n0, n1));
        } else if (tid < 64) {
            float x0 = 0.f, y0 = 0.f, z0 = 0.f, x1 = 0.f, y1 = 0.f, z1 = 0.f;
            if (j0 < N) { const float* q = gt + (base + j0) * 3; x0 = q[0]; y0 = q[1]; z0 = q[2]; }
            if (j1 < N) { const float* q = gt + (base + j1) * 3; x1 = q[0]; y1 = q[1]; z1 = q[2]; }
            float n0 = fmaf(x0, x0, fmaf(y0, y0, z0 * z0));
            float n1 = fmaf(x1, x1, fmaf(y1, y1, z1 * z1));
            shGa[grp] = make_ulonglong2(packf2(-2.f * x0, -2.f * x1),
                                        packf2(-2.f * y0, -2.f * y1));
            shGb[grp] = make_ulonglong2(packf2(-2.f * z0, -2.f * z1),
                                        packf2(n0, n1));
        } else if (tid < 96) {
            float w0 = (j0 < N) ? w[base + j0] : 0.f;   // w=0 -> no contribution
            float w1 = (j1 < N) ? w[base + j1] : 0.f;
            shw[grp] = packf2(w0, w1);
        }
    }

    int i = ti * JT + tid;
    float xi = 0.f, yi = 0.f, zi = 0.f, gxi = 0.f, gyi = 0.f, gzi = 0.f, wi = 0.f;
    if (i < N) {
        const float* pi = p  + (base + i) * 3;
        const float* gi = gt + (base + i) * 3;
        xi = pi[0]; yi = pi[1]; zi = pi[2];
        gxi = gi[0]; gyi = gi[1]; gzi = gi[2];
        wi = w[base + i];
    }
    float spi = fmaf(xi, xi, fmaf(yi, yi, zi * zi));
    float sgi = fmaf(gxi, gxi, fmaf(gyi, gyi, gzi * gzi));

    // broadcast i-point into packed lanes
    unsigned long long xi2  = packf2(xi, xi),   yi2  = packf2(yi, yi),   zi2  = packf2(zi, zi);
    unsigned long long gxi2 = packf2(gxi, gxi), gyi2 = packf2(gyi, gyi), gzi2 = packf2(gzi, gzi);
    unsigned long long spi2 = packf2(spi, spi), sgi2 = packf2(sgi, sgi);
    __syncthreads();

    unsigned long long acc2 = 0ULL;
    #pragma unroll 8
    for (int jj = 0; jj < JG; jj++) {
        ulonglong2 Pa = shPa[jj];
        ulonglong2 Pb = shPb[jj];
        unsigned long long t;
        ADD2(t, spi2, Pb.y);          // spi + |pj|^2   (both lanes)
        FMA2(t, Pa.x, xi2, t);        // -2 px*xi
        FMA2(t, Pa.y, yi2, t);
        FMA2(t, Pb.x, zi2, t);        // t = dp^2 pair
        ulonglong2 Ga = shGa[jj];
        ulonglong2 Gb = shGb[jj];
        unsigned long long u;
        ADD2(u, sgi2, Gb.y);
        FMA2(u, Ga.x, gxi2, u);
        FMA2(u, Ga.y, gyi2, u);
        FMA2(u, Gb.x, gzi2, u);       // u = dg^2 pair
        unsigned long long prod;
        MUL2(prod, t, u);
        float p0, p1;
        unpackf2(p0, p1, prod);
        float s0 = fsqrt_fast(fmaxf(p0, 0.f));   // dp*dg with ONE sqrt per pair
        float s1 = fsqrt_fast(fmaxf(p1, 0.f));
        unsigned long long s2 = packf2(s0, s1);
        FMA2(acc2, shw[jj], s2, acc2);
    }
    float a0, a1;
    unpackf2(a0, a1, acc2);
    float factor = (ti == tj) ? 1.0f : 2.0f;
    float acc = (a0 + a1) * (wi * factor);

    float tot = block_reduce_f(acc);
    if (tid == 0) g_cross_part[(b * ntri + k) * SPLIT + sub] = tot;

    // Diagonal tiles (one split only) also compute the 18 weighted moments for
    // their i-range (one point per thread, already resident in registers).
    if (ti == tj && sub == 0) {
        float m[18];
        float wpx = wi * xi, wpy = wi * yi, wpz = wi * zi;
        m[0]  = wi;
        m[1]  = wpx; m[2]  = wpy; m[3]  = wpz;
        m[4]  = wi * gxi; m[5]  = wi * gyi; m[6]  = wi * gzi;
        m[7]  = wpx * gxi; m[8]  = wpx * gyi; m[9]  = wpx * gzi;
        m[10] = wpy * gxi; m[11] = wpy * gyi; m[12] = wpy * gzi;
        m[13] = wpz * gxi; m[14] = wpz * gyi; m[15] = wpz * gzi;
        m[16] = wi * spi;
        m[17] = wi * sgi;

        #pragma unroll
        for (int kk = 0; kk < 18; kk++) {
            #pragma unroll
            for (int o = 16; o > 0; o >>= 1)
                m[kk] += __shfl_down_sync(0xffffffffu, m[kk], o);
        }
        int lane = tid & 31, wid = tid >> 5;
        if (lane == 0) {
            #pragma unroll
            for (int kk = 0; kk < 18; kk++) smom[wid][kk] = m[kk];
        }
        __syncthreads();
        if (tid < 18)
            g_mom_part[b][ti][tid] =
                smom[0][tid] + smom[1][tid] + smom[2][tid] + smom[3][tid];
    }
}

// ---------------- Kernel 2: moment combine (double) + Kabsch solve (float Jacobi) ----------------
__global__ void solve_kernel(int B, int tiles) {
    __shared__ double S[MAXB][18];
    int t = threadIdx.x;
    if (t < B * 18) {
        int bb = t / 18, kk = t % 18;
        double v = 0.0;
        for (int tt = 0; tt < tiles; tt++) v += (double)g_mom_part[bb][tt][kk];
        S[bb][kk] = v;
    }
    __syncthreads();

    int b = t;
    if (b >= B) return;

    double Sw = S[b][0];
    double invSw = 1.0 / Sw;
    double sp[3] = { S[b][1], S[b][2], S[b][3] };
    double sg[3] = { S[b][4], S[b][5], S[b][6] };

    // Centered cross-covariance in double (cancellation-sensitive step)
    double Md[3][3];
    #pragma unroll
    for (int i = 0; i < 3; i++)
        #pragma unroll
        for (int j = 0; j < 3; j++)
            Md[i][j] = S[b][7 + i * 3 + j] - sp[i] * sg[j] * invSw;

    // Scale-normalize and drop to float
    double mx = 0.0;
    #pragma unroll
    for (int i = 0; i < 3; i++)
        #pragma unroll
        for (int j = 0; j < 3; j++)
            mx = fmax(mx, fabs(Md[i][j]));
    double invmx = (mx > 0.0) ? 1.0 / mx : 0.0;

    float M[3][3];
    #pragma unroll
    for (int i = 0; i < 3; i++)
        #pragma unroll
        for (int j = 0; j < 3; j++)
            M[i][j] = (float)(Md[i][j] * invmx);

    // A = M^T M (symmetric PSD, entries O(1))
    float A[3][3];
    #pragma unroll
    for (int i = 0; i < 3; i++)
        #pragma unroll
        for (int j = 0; j < 3; j++)
            A[i][j] = M[0][i] * M[0][j] + M[1][i] * M[1][j] + M[2][i] * M[2][j];

    float V[3][3] = {{1, 0, 0}, {0, 1, 0}, {0, 0, 1}};

    // Cyclic Jacobi in float (fixed count -> deterministic)
    for (int sweep = 0; sweep < 12; sweep++) {
        #pragma unroll
        for (int pair = 0; pair < 3; pair++) {
            int pp = (pair == 2) ? 1 : 0;
            int qq = (pair == 0) ? 1 : 2;
            float apq = A[pp][qq];
            if (fabsf(apq) < 1e-20f) continue;
            float theta = (A[qq][qq] - A[pp][pp]) / (2.0f * apq);
            float tt = ((theta >= 0.0f) ? 1.0f : -1.0f) /
                       (fabsf(theta) + fsqrt_fast(fmaf(theta, theta, 1.0f)));
            float c = rsqrtf(fmaf(tt, tt, 1.0f));
            float s = tt * c;
            float app = A[pp][pp], aq2 = A[qq][qq];
            A[pp][pp] = app - tt * apq;
            A[qq][qq] = aq2 + tt * apq;
            A[pp][qq] = A[qq][pp] = 0.0f;
            int r = 3 - pp - qq;
            float arp = A[r][pp], arq = A[r][qq];
            A[r][pp] = A[pp][r] = c * arp - s * arq;
            A[r][qq] = A[qq][r] = s * arp + c * arq;
            #pragma unroll
            for (int kk = 0; kk < 3; kk++) {
                float vkp = V[kk][pp], vkq = V[kk][qq];
                V[kk][pp] = c * vkp - s * vkq;
                V[kk][qq] = s * vkp + c * vkq;
            }
        }
    }

    // Sort eigenvalues descending
    float lam[3] = { A[0][0], A[1][1], A[2][2] };
    int id[3] = {0, 1, 2};
    if (lam[id[0]] < lam[id[1]]) { int x = id[0]; id[0] = id[1]; id[1] = x; }
    if (lam[id[0]] < lam[id[2]]) { int x = id[0]; id[0] = id[2]; id[2] = x; }
    if (lam[id[1]] < lam[id[2]]) { int x = id[1]; id[1] = id[2]; id[2] = x; }

    // U columns: u_k = normalize(M v_k) for k=0,1; u_2 = u_0 x u_1 (det flip absorbed)
    float U[3][3];
    #pragma unroll
    for (int kk = 0; kk < 2; kk++) {
        float v0 = V[0][id[kk]], v1 = V[1][id[kk]], v2 = V[2][id[kk]];
        float u0 = M[0][0] * v0 + M[0][1] * v1 + M[0][2] * v2;
        float u1 = M[1][0] * v0 + M[1][1] * v1 + M[1][2] * v2;
        float u2 = M[2][0] * v0 + M[2][1] * v1 + M[2][2] * v2;
        float inv = rsqrtf(fmaxf(u0 * u0 + u1 * u1 + u2 * u2, 1e-30f));
        U[0][kk] = u0 * inv; U[1][kk] = u1 * inv; U[2][kk] = u2 * inv;
    }
    U[0][2] = U[1][0] * U[2][1] - U[2][0] * U[1][1];
    U[1][2] = U[2][0] * U[0][1] - U[0][0] * U[2][1];
    U[2][2] = U[0][0] * U[1][1] - U[1][0] * U[0][1];

    #pragma unroll
    for (int i = 0; i < 3; i++)
        #pragma unroll
        for (int j = 0; j < 3; j++)
            g_R[b][i * 3 + j] = U[i][0] * V[j][id[0]] + U[i][1] * V[j][id[1]] + U[i][2] * V[j][id[2]];

    #pragma unroll
    for (int i = 0; i < 3; i++) {
        g_mup[b][i] = (float)(sp[i] * invSw);
        g_mug[b][i] = (float)(sg[i] * invSw);
    }

    g_Sw[b] = Sw;
    // Analytic part of bond numerator: sum_ij wi wj (dp^2 + dg^2)
    g_analytic[b] = 2.0 * Sw * (S[b][16] + S[b][17])
                  - 2.0 * (sp[0] * sp[0] + sp[1] * sp[1] + sp[2] * sp[2]
                         + sg[0] * sg[0] + sg[1] * sg[1] + sg[2] * sg[2]);
}

// ---------------- Kernel 3: point loss + final combine (last-block pattern) ----------------
// grid: (chunks, B), block: 256
__global__ void pts_final_kernel(const float* __restrict__ p, const float* __restrict__ gt,
                                 const float* __restrict__ w, const float* __restrict__ ht,
                                 float* __restrict__ out, int N, int B, int ncross, int outn) {
    int b = blockIdx.y;
    const float* pb = p  + (size_t)b * N * 3;
    const float* gb = gt + (size_t)b * N * 3;
    const float* wb = w  + (size_t)b * N;

    float r00 = g_R[b][0], r01 = g_R[b][1], r02 = g_R[b][2];
    float r10 = g_R[b][3], r11 = g_R[b][4], r12 = g_R[b][5];
    float r20 = g_R[b][6], r21 = g_R[b][7], r22 = g_R[b][8];
    float m0 = g_mup[b][0], m1 = g_mup[b][1], m2 = g_mup[b][2];
    float u0 = g_mug[b][0], u1 = g_mug[b][1], u2 = g_mug[b][2];

    float acc = 0.0f;
    int i = blockIdx.x * blockDim.x + threadIdx.x;
    if (i < N) {
        float gx = gb[3 * i]     - u0;
        float gy = gb[3 * i + 1] - u1;
        float gz = gb[3 * i + 2] - u2;
        float ax = fmaf(r00, gx, fmaf(r01, gy, r02 * gz)) + m0;
        float ay = fmaf(r10, gx, fmaf(r11, gy, r12 * gz)) + m1;
        float az = fmaf(r20, gx, fmaf(r21, gy, r22 * gz)) + m2;
        float dx = pb[3 * i]     - ax;
        float dy = pb[3 * i + 1] - ay;
        float dz = pb[3 * i + 2] - az;
        float nsq = fmaf(dx, dx, fmaf(dy, dy, dz * dz));
        acc = wb[i] * fsqrt_fast(nsq);
    }
    float tot = block_reduce_f(acc);

    __shared__ int isLast;
    int nblocks = gridDim.x * gridDim.y;
    if (threadIdx.x == 0) {
        g_pts_part[b * gridDim.x + blockIdx.x] = tot;
        __threadfence();
        int old = atomicAdd(&g_count, 1);
        isLast = (old == nblocks - 1) ? 1 : 0;
    }
    __syncthreads();
    if (!isLast) return;

    // ---- final combine (executed by exactly one block; fixed summation order) ----
    double vp = 0.0, vc = 0.0;
    for (int idx = threadIdx.x; idx < nblocks; idx += blockDim.x) vp += (double)g_pts_part[idx];
    for (int idx = threadIdx.x; idx < ncross;  idx += blockDim.x) vc += (double)g_cross_part[idx];

    __shared__ double rp[256];
    __shared__ double rc[256];
    rp[threadIdx.x] = vp;
    rc[threadIdx.x] = vc;
    __syncthreads();
    for (int off = 128; off > 0; off >>= 1) {
        if (threadIdx.x < off) {
            rp[threadIdx.x] += rp[threadIdx.x + off];
            rc[threadIdx.x] += rc[threadIdx.x + off];
        }
        __syncthreads();
    }

    __shared__ double loss_sh;
    if (threadIdx.x == 0) {
        double totW = 0.0, den = 0.0, an = 0.0;
        for (int bb = 0; bb < B; bb++) {
            double s = g_Sw[bb];
            totW += s;
            den  += s * s;
            an   += g_analytic[bb];
        }
        double loss_pts  = rp[0] / totW;
        double loss_bond = (an - 2.0 * rc[0]) / den;
        loss_sh = loss_pts + 1.0 * loss_bond;   // ALPHA_BOND = 1
        g_count = 0;                            // self-reset for next replay
    }
    __syncthreads();
    int bb = threadIdx.x;
    if (bb < outn && bb < B) {
        double h = (double)ht[bb];
        out[bb] = (float)((h * h + 256.0) / ((h + 16.0) * (h + 16.0)) * loss_sh);
    }
}

// ---------------- launcher ----------------
extern "C" void kernel_launch(void* const* d_in, const int* in_sizes, int n_in,
                              void* d_out, int out_size) {
    const float* p  = (const float*)d_in[0];  // xpred_l [B,N,3]
    const float* g  = (const float*)d_in[1];  // xGT_l   [B,N,3]
    const float* ht = (const float*)d_in[2];  // ht      [B]
    const float* w  = (const float*)d_in[3];  // w_l     [B,N]

    int B = in_sizes[2];
    if (B > MAXB) B = MAXB;
    int N = in_sizes[3] / B;

    int tiles = (N + JT - 1) / JT;
    if (tiles > MAXTILES) tiles = MAXTILES;   // (inputs are B=4, N=2048 -> 16 tiles)
    int ntri = tiles * (tiles + 1) / 2;
    int ncross = B * ntri * SPLIT;

    bond_kernel<<<dim3(ntri, SPLIT, B), JT>>>(p, g, w, N, ntri);
    solve_kernel<<<1, 160>>>(B, tiles);

    int chunks = (N + 255) / 256;
    pts_final_kernel<<<dim3(chunks, B), 256>>>(p, g, w, ht, (float*)d_out,
                                               N, B, ncross, out_size);
}